// round 8
// baseline (speedup 1.0000x reference)
#include <cuda_runtime.h>
#include <cstdint>

#define B 32
#define HW 512
#define NPIX (HW * HW)
#define NPATCH 4
#define C 3
#define P 128
#define HALF 64
#define MARGIN 32
#define TILE 32
#define TPD (HW / TILE)          // 16
#define NTILE (TPD * TPD)        // 256
#define NHALF (NTILE * 2)        // 512 half-tiles (16 rows x 32 cols)
#define PATCH_OUT_ELEMS (B * NPATCH * C * P * P)

#define TM_BLOCKS 1024           // single wave: <= 148*8
#define EX_BLOCKS 768            // single wave; 1536 quarter-tasks / 768 = 2 each

__device__ unsigned long long g_half[B * NHALF];
__device__ int g_boxes[B * NPATCH * 4];

__device__ __forceinline__ unsigned flipf(float v) {
    unsigned ub = __float_as_uint(v);
    return (ub & 0x80000000u) ? ~ub : (ub | 0x80000000u);
}

// ---------------------------------------------------------------------------
// Pass A: warp-per-half-tile argmax, 2 sequential tasks per warp.
// 1024 blocks x 256 thr = one uniform wave. redux.sync reduce.
// ---------------------------------------------------------------------------
__global__ __launch_bounds__(256)
void k_tilemax(const float* __restrict__ umap) {
    const int lane = threadIdx.x & 31;
    const int w = blockIdx.x * 8 + (threadIdx.x >> 5);   // 0..8191

#pragma unroll
    for (int rep = 0; rep < 2; rep++) {
        const int task = w + rep * 8192;                 // 0..16383
        const int b = task >> 9;
        const int hid = task & 511;
        const int tile = hid >> 1;
        const int tx1 = (tile & (TPD - 1)) * TILE;
        const int ty1 = ((tile >> 4) * TILE) + ((hid & 1) << 4);
        const float* __restrict__ um = umap + ((size_t)b << 18);

        float4 f[4];
#pragma unroll
        for (int q = 0; q < 4; q++) {
            const int f4 = q * 32 + lane;                // 0..127
            const int y = ty1 + (f4 >> 3);
            const int x = tx1 + ((f4 & 7) << 2);
            f[q] = *(const float4*)(um + (y << 9) + x);
        }

        float c4[4];
#pragma unroll
        for (int q = 0; q < 4; q++)
            c4[q] = fmaxf(fmaxf(f[q].x, f[q].y), fmaxf(f[q].z, f[q].w));
        const float m = fmaxf(fmaxf(c4[0], c4[1]), fmaxf(c4[2], c4[3]));

        const unsigned fm = flipf(m);
        const unsigned rmax = __reduce_max_sync(0xFFFFFFFFu, fm);

        int idx = 0x7FFFFFFF;
        if (fm == rmax) {
#pragma unroll
            for (int q = 0; q < 4; q++) {
                if (c4[q] == m) {
                    const int f4 = q * 32 + lane;
                    const int gi = ((ty1 + (f4 >> 3)) << 9) + tx1 + ((f4 & 7) << 2);
                    if (f[q].x == m) idx = min(idx, gi);
                    if (f[q].y == m) idx = min(idx, gi + 1);
                    if (f[q].z == m) idx = min(idx, gi + 2);
                    if (f[q].w == m) idx = min(idx, gi + 3);
                }
            }
        }
        const unsigned rid = __reduce_min_sync(0xFFFFFFFFu, (unsigned)idx);

        if (lane == 0)
            g_half[b * NHALF + hid] =
                ((unsigned long long)rmax << 32) | (unsigned)~rid;
    }
}

// ---------------------------------------------------------------------------
// Pass B: fused 4-round greedy selection. One 1024-thr block per batch.
// ---------------------------------------------------------------------------
__global__ __launch_bounds__(1024)
void k_select(const float* __restrict__ umap, float* __restrict__ out_coords) {
    const int b = blockIdx.x;
    const int t = threadIdx.x;
    const int lane = t & 31, wid = t >> 5;
    const float* __restrict__ um = umap + ((size_t)b << 18);

    __shared__ unsigned long long stile[NTILE];
    __shared__ unsigned long long sred[32];
    __shared__ int sebox[NPATCH][4];    // expanded (±MARGIN)
    __shared__ int slist[64];
    __shared__ int scount;

    if (t < NTILE) {
        const unsigned long long a = g_half[b * NHALF + 2 * t];
        const unsigned long long c = g_half[b * NHALF + 2 * t + 1];
        stile[t] = (a > c) ? a : c;     // packed order preserves first-occurrence
    }

    for (int k = 0; k < NPATCH; k++) {
        __syncthreads();
        unsigned long long v = (t < NTILE) ? stile[t] : 0ULL;
#pragma unroll
        for (int off = 16; off > 0; off >>= 1) {
            unsigned long long o = __shfl_down_sync(0xFFFFFFFFu, v, off);
            v = (o > v) ? o : v;
        }
        if (lane == 0) sred[wid] = v;
        __syncthreads();
        if (t == 0) {
            unsigned long long w = sred[0];
#pragma unroll
            for (int j = 1; j < 8; j++) w = (sred[j] > w) ? sred[j] : w;
            const int idx = (int)(~(unsigned)(w & 0xFFFFFFFFu));
            const int yc = idx >> 9, xc = idx & (HW - 1);

            int x1 = max(0, xc - HALF), x2 = min(HW, xc + HALF);
            if (x2 - x1 < P) { if (x1 == 0) x2 = P; else x1 = x2 - P; }
            int y1 = max(0, yc - HALF), y2 = min(HW, yc + HALF);
            if (y2 - y1 < P) { if (y1 == 0) y2 = P; else y1 = y2 - P; }

            sebox[k][0] = x1 - MARGIN; sebox[k][1] = y1 - MARGIN;
            sebox[k][2] = x2 + MARGIN; sebox[k][3] = y2 + MARGIN;

            int* bx = &g_boxes[(b * NPATCH + k) * 4];
            bx[0] = x1; bx[1] = y1; bx[2] = x2; bx[3] = y2;
            float* oc = out_coords + (b * NPATCH + k) * 4;
            oc[0] = (float)x1; oc[1] = (float)y1;
            oc[2] = (float)x2; oc[3] = (float)y2;
            scount = 0;
        }
        __syncthreads();
        if (k == NPATCH - 1) break;

        // classify tiles vs newly added expanded box
        if (t < NTILE) {
            const int ex1 = sebox[k][0], ey1 = sebox[k][1];
            const int ex2 = sebox[k][2], ey2 = sebox[k][3];
            const int tx1 = (t & (TPD - 1)) * TILE, ty1 = (t >> 4) * TILE;
            const int tx2 = tx1 + TILE, ty2 = ty1 + TILE;
            if ((tx1 < ex2) && (tx2 > ex1) && (ty1 < ey2) && (ty2 > ey1)) {
                if ((tx1 >= ex1) && (tx2 <= ex2) && (ty1 >= ey1) && (ty2 <= ey2))
                    stile[t] = 0ULL;
                else
                    slist[atomicAdd(&scount, 1)] = t;
            }
        }
        __syncthreads();

        // warp-per-tile rescan of boundary tiles against boxes 0..k
        const int cnt = scount;
        for (int li = wid; li < cnt; li += 32) {
            const int tile = slist[li];
            const int tx1 = (tile & (TPD - 1)) * TILE;
            const int ty1 = (tile >> 4) * TILE;

            float4 f[8];
#pragma unroll
            for (int q = 0; q < 8; q++) {
                const int f4 = q * 32 + lane;
                const int y = ty1 + (f4 >> 3);
                const int x = tx1 + ((f4 & 7) << 2);
                f[q] = *(const float4*)(um + (y << 9) + x);
            }

            float m = -3.4e38f; int idx = 0;
#pragma unroll
            for (int q = 0; q < 8; q++) {
                const int f4 = q * 32 + lane;
                const int y = ty1 + (f4 >> 3);
                const int x = tx1 + ((f4 & 7) << 2);
                unsigned mask = 0;
                for (int j = 0; j <= k; j++) {
                    if (y >= sebox[j][1] && y < sebox[j][3]) {
                        const int lo = max(sebox[j][0] - x, 0);
                        const int hi = min(sebox[j][2] - x, 4);
                        if (hi > lo) mask |= ((1u << (hi - lo)) - 1u) << lo;
                    }
                }
                const int gi = (y << 9) + x;
                const float vals[4] = {f[q].x, f[q].y, f[q].z, f[q].w};
#pragma unroll
                for (int e = 0; e < 4; e++)
                    if (!((mask >> e) & 1u) && vals[e] > m) { m = vals[e]; idx = gi + e; }
            }

            unsigned long long best =
                ((unsigned long long)flipf(m) << 32) | (unsigned)~(unsigned)idx;
#pragma unroll
            for (int off = 16; off > 0; off >>= 1) {
                unsigned long long o = __shfl_down_sync(0xFFFFFFFFu, best, off);
                best = (o > best) ? o : best;
            }
            if (lane == 0) stile[tile] = best;
        }
    }
}

// ---------------------------------------------------------------------------
// Pass C: extract. 768 blocks x 256 thr, 2 uniform quarter-tasks per block.
// Streaming stores (.cs) keep L2 for reads.
// ---------------------------------------------------------------------------
__global__ __launch_bounds__(256)
void k_extract(const float* __restrict__ images, float* __restrict__ out) {
#pragma unroll
    for (int rep = 0; rep < 2; rep++) {
        const int task = blockIdx.x + rep * EX_BLOCKS;   // 0..1535
        const int sub = task & 3;                        // quarter (32 rows)
        const int pc = task >> 2;
        const int c = pc % C;
        const int n = (pc / C) % NPATCH;
        const int b = pc / (C * NPATCH);

        const int x1 = g_boxes[(b * NPATCH + n) * 4 + 0];
        const int y1 = g_boxes[(b * NPATCH + n) * 4 + 1];

        const float* __restrict__ src =
            images + (((size_t)(b * C + c) * HW) + y1 + sub * 32) * HW + x1;
        float4* __restrict__ dst =
            (float4*)(out + (size_t)((b * NPATCH + n) * C + c) * (P * P)) + sub * 1024;

        float4 r[4];
#pragma unroll
        for (int it = 0; it < 4; it++) {
            const int v = it * 256 + threadIdx.x;        // 0..1023 f4
            const int i = v >> 5;                        // row 0..31
            const int j = (v & 31) * 4;                  // col
            const float* s = src + (size_t)i * HW + j;
            r[it] = make_float4(s[0], s[1], s[2], s[3]);
        }
#pragma unroll
        for (int it = 0; it < 4; it++)
            __stcs(&dst[it * 256 + threadIdx.x], r[it]);
    }
}

// ---------------------------------------------------------------------------
extern "C" void kernel_launch(void* const* d_in, const int* in_sizes, int n_in,
                              void* d_out, int out_size) {
    const float* images = (const float*)d_in[0];   // [32,3,512,512]
    const float* umaps  = (const float*)d_in[1];   // [32,1,512,512]
    float* out = (float*)d_out;
    float* out_coords = out + PATCH_OUT_ELEMS;

    k_tilemax<<<TM_BLOCKS, 256>>>(umaps);
    k_select<<<B, 1024>>>(umaps, out_coords);
    k_extract<<<EX_BLOCKS, 256>>>(images, out);
}